// round 1
// baseline (speedup 1.0000x reference)
#include <cuda_runtime.h>

#define B_TOTAL   131072
#define ROW_F     240
#define NBLOCKS   2048
#define NTHREADS  256
#define WPB       8          // warps per block

// deterministic two-stage reduction scratch (no allocation allowed)
__device__ double g_partials[NBLOCKS * 2];

__global__ __launch_bounds__(NTHREADS)
void constraint_loss_main(const float* __restrict__ pred,
                          const float* __restrict__ tgt,
                          const float* __restrict__ inp)
{
    __shared__ float  s_pred[WPB][ROW_F];   // staged prediction row per warp
    __shared__ double s_red[WPB][2];

    const int warp = threadIdx.x >> 5;
    const int lane = threadIdx.x & 31;
    const int gwarp = blockIdx.x * WPB + warp;
    const int totalWarps = gridDim.x * WPB;

    float  mse_acc = 0.0f;
    double con_acc = 0.0;

    for (int row = gwarp; row < B_TOTAL; row += totalWarps) {
        const float4* p4 = (const float4*)(pred + (size_t)row * ROW_F);
        const float4* t4 = (const float4*)(tgt  + (size_t)row * ROW_F);
        float4* s4 = (float4*)s_pred[warp];

        // ---- phase 1: coalesced stream of pred/tgt, fused MSE, stage pred ----
        #pragma unroll
        for (int j = lane; j < 60; j += 32) {          // 60 float4 per row
            float4 p = p4[j];
            float4 t = t4[j];
            float d0 = p.x - t.x, d1 = p.y - t.y;
            float d2 = p.z - t.z, d3 = p.w - t.w;
            mse_acc += d0 * d0 + d1 * d1 + d2 * d2 + d3 * d3;
            s4[j] = p;
        }

        // ---- inputs row (13 floats, uniform across warp -> broadcast loads) ----
        const float* irow = inp + (size_t)row * 13;
        float x0_0 = irow[0],  x0_1 = irow[1],  x0_2 = irow[2], x0_3 = irow[3];
        float o0x = irow[4],  o0y = irow[5],  o0r = irow[6];
        float o1x = irow[7],  o1y = irow[8],  o1r = irow[9];
        float o2x = irow[10], o2y = irow[11], o2r = irow[12];
        float rad2_0 = (o0r + 2.0f) * (o0r + 2.0f);
        float rad2_1 = (o1r + 2.0f) * (o1r + 2.0f);
        float rad2_2 = (o2r + 2.0f) * (o2r + 2.0f);

        __syncwarp();

        // ---- phase 2: timesteps distributed over lanes ----
        float r0 = 0.f, r1 = 0.f, r2 = 0.f, r3 = 0.f, ob = 0.f;
        #pragma unroll
        for (int k = lane; k < 40; k += 32) {
            const float* xk = &s_pred[warp][4 * k];
            float xk0 = xk[0], xk1 = xk[1], xk2 = xk[2], xk3 = xk[3];

            float p0, p1, p2, p3;
            if (k == 0) {
                p0 = x0_0; p1 = x0_1; p2 = x0_2; p3 = x0_3;
            } else {
                const float* pk = &s_pred[warp][4 * (k - 1)];
                p0 = pk[0]; p1 = pk[1]; p2 = pk[2]; p3 = pk[3];
            }
            float u0 = s_pred[warp][160 + 2 * k];
            float u1 = s_pred[warp][161 + 2 * k];

            float c, s;
            sincosf(p2, &s, &c);
            r0 += xk0 - (p0 + p3 * c * 0.25f);
            r1 += xk1 - (p1 + p3 * s * 0.25f);
            r2 += xk2 - (p2 + u1 * 0.25f);
            r3 += xk3 - (p3 + u0 * 0.25f);

            float dx, dy;
            dx = xk0 - o0x; dy = xk1 - o0y;
            ob += sqrtf(dx * dx + dy * dy) - rad2_0;
            dx = xk0 - o1x; dy = xk1 - o1y;
            ob += sqrtf(dx * dx + dy * dy) - rad2_1;
            dx = xk0 - o2x; dy = xk1 - o2y;
            ob += sqrtf(dx * dx + dy * dy) - rad2_2;
        }

        // ---- warp reduce residual 4-vector + obstacle sum ----
        #pragma unroll
        for (int off = 16; off; off >>= 1) {
            r0 += __shfl_xor_sync(0xFFFFFFFFu, r0, off);
            r1 += __shfl_xor_sync(0xFFFFFFFFu, r1, off);
            r2 += __shfl_xor_sync(0xFFFFFFFFu, r2, off);
            r3 += __shfl_xor_sync(0xFFFFFFFFu, r3, off);
            ob += __shfl_xor_sync(0xFFFFFFFFu, ob, off);
        }
        if (lane == 0) {
            float dyn = sqrtf(r0 * r0 + r1 * r1 + r2 * r2 + r3 * r3);
            con_acc += (double)(dyn + ob);
        }
        __syncwarp();   // protect s_pred before next row overwrites it
    }

    // ---- warp reduce mse, block collect, write deterministic partials ----
    #pragma unroll
    for (int off = 16; off; off >>= 1)
        mse_acc += __shfl_xor_sync(0xFFFFFFFFu, mse_acc, off);

    if (lane == 0) {
        s_red[warp][0] = (double)mse_acc;
        s_red[warp][1] = con_acc;
    }
    __syncthreads();
    if (threadIdx.x == 0) {
        double m = 0.0, c = 0.0;
        #pragma unroll
        for (int w = 0; w < WPB; w++) { m += s_red[w][0]; c += s_red[w][1]; }
        g_partials[blockIdx.x * 2 + 0] = m;
        g_partials[blockIdx.x * 2 + 1] = c;
    }
}

__global__ void constraint_loss_finalize(float* __restrict__ out)
{
    __shared__ double sm[256];
    __shared__ double sc[256];
    double m = 0.0, c = 0.0;
    for (int i = threadIdx.x; i < NBLOCKS; i += 256) {
        m += g_partials[2 * i + 0];
        c += g_partials[2 * i + 1];
    }
    sm[threadIdx.x] = m;
    sc[threadIdx.x] = c;
    __syncthreads();
    for (int s = 128; s > 0; s >>= 1) {
        if (threadIdx.x < s) {
            sm[threadIdx.x] += sm[threadIdx.x + s];
            sc[threadIdx.x] += sc[threadIdx.x + s];
        }
        __syncthreads();
    }
    if (threadIdx.x == 0) {
        double mse  = sm[0] / ((double)B_TOTAL * (double)ROW_F);
        double con  = sc[0] / (double)B_TOTAL;
        out[0] = (float)(mse + con);
    }
}

extern "C" void kernel_launch(void* const* d_in, const int* in_sizes, int n_in,
                              void* d_out, int out_size)
{
    const float* pred = (const float*)d_in[0];
    const float* tgt  = (const float*)d_in[1];
    const float* inp  = (const float*)d_in[2];
    float* out = (float*)d_out;

    constraint_loss_main<<<NBLOCKS, NTHREADS>>>(pred, tgt, inp);
    constraint_loss_finalize<<<1, 256>>>(out);
}

// round 2
// speedup vs baseline: 1.0732x; 1.0732x over previous
#include <cuda_runtime.h>

#define B_TOTAL   131072
#define ROW_F     240
#define NBLOCKS   2048
#define NTHREADS  256
#define WPB       8          // warps per block

// deterministic two-stage reduction scratch (no allocation allowed)
__device__ double   g_partials[NBLOCKS * 2];
__device__ unsigned g_count = 0;

__global__ __launch_bounds__(NTHREADS)
void constraint_loss_fused(const float* __restrict__ pred,
                           const float* __restrict__ tgt,
                           const float* __restrict__ inp,
                           float* __restrict__ out)
{
    __shared__ float  s_pred[WPB][ROW_F];   // staged prediction row per warp
    __shared__ double s_red[WPB][2];
    __shared__ bool   s_is_last;

    const int warp = threadIdx.x >> 5;
    const int lane = threadIdx.x & 31;
    const int gwarp = blockIdx.x * WPB + warp;
    const int totalWarps = gridDim.x * WPB;

    float  mse_acc = 0.0f;
    double con_acc = 0.0;

    for (int row = gwarp; row < B_TOTAL; row += totalWarps) {
        const float4* p4 = (const float4*)(pred + (size_t)row * ROW_F);
        const float4* t4 = (const float4*)(tgt  + (size_t)row * ROW_F);
        float4* s4 = (float4*)s_pred[warp];

        // ---- phase 1: coalesced stream of pred/tgt, fused MSE, stage pred ----
        #pragma unroll
        for (int j = lane; j < 60; j += 32) {          // 60 float4 per row
            float4 p = p4[j];
            float4 t = t4[j];
            float d0 = p.x - t.x, d1 = p.y - t.y;
            float d2 = p.z - t.z, d3 = p.w - t.w;
            mse_acc += d0 * d0 + d1 * d1 + d2 * d2 + d3 * d3;
            s4[j] = p;
        }

        // ---- inputs row (13 floats, uniform across warp -> broadcast loads) ----
        const float* irow = inp + (size_t)row * 13;
        float x0_0 = irow[0],  x0_1 = irow[1],  x0_2 = irow[2], x0_3 = irow[3];
        float o0x = irow[4],  o0y = irow[5],  o0r = irow[6];
        float o1x = irow[7],  o1y = irow[8],  o1r = irow[9];
        float o2x = irow[10], o2y = irow[11], o2r = irow[12];
        float rad2_0 = (o0r + 2.0f) * (o0r + 2.0f);
        float rad2_1 = (o1r + 2.0f) * (o1r + 2.0f);
        float rad2_2 = (o2r + 2.0f) * (o2r + 2.0f);

        __syncwarp();

        // ---- phase 2: timesteps distributed over lanes ----
        float r0 = 0.f, r1 = 0.f, r2 = 0.f, r3 = 0.f, ob = 0.f;
        #pragma unroll
        for (int k = lane; k < 40; k += 32) {
            const float* xk = &s_pred[warp][4 * k];
            float xk0 = xk[0], xk1 = xk[1], xk2 = xk[2], xk3 = xk[3];

            float p0, p1, p2, p3;
            if (k == 0) {
                p0 = x0_0; p1 = x0_1; p2 = x0_2; p3 = x0_3;
            } else {
                const float* pk = &s_pred[warp][4 * (k - 1)];
                p0 = pk[0]; p1 = pk[1]; p2 = pk[2]; p3 = pk[3];
            }
            float u0 = s_pred[warp][160 + 2 * k];
            float u1 = s_pred[warp][161 + 2 * k];

            float c, s;
            __sincosf(p2, &s, &c);                 // MUFU fast path
            r0 += xk0 - (p0 + p3 * c * 0.25f);
            r1 += xk1 - (p1 + p3 * s * 0.25f);
            r2 += xk2 - (p2 + u1 * 0.25f);
            r3 += xk3 - (p3 + u0 * 0.25f);

            float dx, dy;
            dx = xk0 - o0x; dy = xk1 - o0y;
            ob += sqrtf(dx * dx + dy * dy) - rad2_0;
            dx = xk0 - o1x; dy = xk1 - o1y;
            ob += sqrtf(dx * dx + dy * dy) - rad2_1;
            dx = xk0 - o2x; dy = xk1 - o2y;
            ob += sqrtf(dx * dx + dy * dy) - rad2_2;
        }

        // ---- warp reduce residual 4-vector + obstacle sum ----
        #pragma unroll
        for (int off = 16; off; off >>= 1) {
            r0 += __shfl_xor_sync(0xFFFFFFFFu, r0, off);
            r1 += __shfl_xor_sync(0xFFFFFFFFu, r1, off);
            r2 += __shfl_xor_sync(0xFFFFFFFFu, r2, off);
            r3 += __shfl_xor_sync(0xFFFFFFFFu, r3, off);
            ob += __shfl_xor_sync(0xFFFFFFFFu, ob, off);
        }
        if (lane == 0) {
            float dyn = sqrtf(r0 * r0 + r1 * r1 + r2 * r2 + r3 * r3);
            con_acc += (double)(dyn + ob);
        }
        __syncwarp();   // protect s_pred before next row overwrites it
    }

    // ---- warp reduce mse, block collect, write deterministic partials ----
    #pragma unroll
    for (int off = 16; off; off >>= 1)
        mse_acc += __shfl_xor_sync(0xFFFFFFFFu, mse_acc, off);

    if (lane == 0) {
        s_red[warp][0] = (double)mse_acc;
        s_red[warp][1] = con_acc;
    }
    __syncthreads();
    if (threadIdx.x == 0) {
        double m = 0.0, c = 0.0;
        #pragma unroll
        for (int w = 0; w < WPB; w++) { m += s_red[w][0]; c += s_red[w][1]; }
        g_partials[blockIdx.x * 2 + 0] = m;
        g_partials[blockIdx.x * 2 + 1] = c;
        __threadfence();
        unsigned ticket = atomicAdd(&g_count, 1u);
        s_is_last = (ticket == (unsigned)(gridDim.x - 1));
    }
    __syncthreads();

    // ---- last block: deterministic fixed-order final sum ----
    if (s_is_last) {
        __threadfence();                 // acquire all partials
        __shared__ double sm[NTHREADS];
        __shared__ double sc[NTHREADS];
        double m = 0.0, c = 0.0;
        for (int i = threadIdx.x; i < NBLOCKS; i += NTHREADS) {
            m += g_partials[2 * i + 0];
            c += g_partials[2 * i + 1];
        }
        sm[threadIdx.x] = m;
        sc[threadIdx.x] = c;
        __syncthreads();
        for (int s = NTHREADS / 2; s > 0; s >>= 1) {
            if (threadIdx.x < s) {
                sm[threadIdx.x] += sm[threadIdx.x + s];
                sc[threadIdx.x] += sc[threadIdx.x + s];
            }
            __syncthreads();
        }
        if (threadIdx.x == 0) {
            double mse = sm[0] / ((double)B_TOTAL * (double)ROW_F);
            double con = sc[0] / (double)B_TOTAL;
            out[0] = (float)(mse + con);
            g_count = 0;                 // reset for next graph replay
        }
    }
}

extern "C" void kernel_launch(void* const* d_in, const int* in_sizes, int n_in,
                              void* d_out, int out_size)
{
    const float* pred = (const float*)d_in[0];
    const float* tgt  = (const float*)d_in[1];
    const float* inp  = (const float*)d_in[2];
    float* out = (float*)d_out;

    constraint_loss_fused<<<NBLOCKS, NTHREADS>>>(pred, tgt, inp, out);
}